// round 2
// baseline (speedup 1.0000x reference)
#include <cuda_runtime.h>
#include <cstdint>
#include <math.h>

#define B_ROWS 32768
#define R_N 4
#define U_N 256
#define D_N 256
#define NX 768  /* 3*U */

// Scratch for GEMM outputs (allowed: __device__ globals, no runtime alloc)
__device__ float g_mx[(size_t)B_ROWS * NX];              // matrix_x  (B, 768)
__device__ float g_inner[(size_t)B_ROWS * R_N * NX];     // matrix_inner (B, 4, 768)

#define BM 128
#define BN 64
#define BK 16
#define AS_LD 132  /* padded leading dim for A tile (transposed) */

// One kernel computes all 5 GEMMs via blockIdx.z:
//   z==0: inputs(B,256) @ kernel(256,768) + bias[0]        -> g_mx
//   z==r+1: states[:,r,:](B,256) @ rkernel[r](256,768) + bias[r+1] -> g_inner[:,r,:]
__global__ void __launch_bounds__(256) gemm5_kernel(
    const float* __restrict__ inputs,
    const float* __restrict__ states,
    const float* __restrict__ kernelW,
    const float* __restrict__ rkernel,
    const float* __restrict__ bias)
{
    const int z = blockIdx.z;
    const float* A;
    int lda;
    const float* W;
    if (z == 0) {
        A = inputs; lda = D_N; W = kernelW;
    } else {
        A = states + (z - 1) * U_N;                 // row b starts at b*1024 + r*256
        lda = R_N * U_N;
        W = rkernel + (size_t)(z - 1) * U_N * NX;
    }
    const float* brow = bias + z * NX;

    const int block_row = blockIdx.y * BM;
    const int block_col = blockIdx.x * BN;

    __shared__ float As[BK * AS_LD];   // stored transposed: As[k][row]
    __shared__ float Bs[BK * BN];      // Bs[k][n]

    const int tid = threadIdx.x;
    const int tr = tid >> 4;           // 0..15 -> rows tr*8..tr*8+7
    const int tc = tid & 15;           // 0..15 -> cols tc*4..tc*4+3
    const int ka = tid & 15;           // A-load: k within tile
    const int ra = tid >> 4;           // A-load: base row (16 rows/pass, 8 passes)
    const int nb = tid & 63;           // B-load: col
    const int kb = tid >> 6;           // B-load: base k (4 rows/pass, 4 passes)

    float acc[8][4];
#pragma unroll
    for (int i = 0; i < 8; i++)
#pragma unroll
        for (int j = 0; j < 4; j++) acc[i][j] = 0.f;

    for (int k0 = 0; k0 < D_N; k0 += BK) {
#pragma unroll
        for (int p = 0; p < 8; p++) {
            int row = ra + p * 16;
            As[ka * AS_LD + row] = A[(size_t)(block_row + row) * lda + k0 + ka];
        }
#pragma unroll
        for (int p = 0; p < 4; p++) {
            int kk = kb + p * 4;
            Bs[kk * BN + nb] = W[(size_t)(k0 + kk) * NX + block_col + nb];
        }
        __syncthreads();
#pragma unroll
        for (int kk = 0; kk < BK; kk++) {
            float4 a0 = *(const float4*)&As[kk * AS_LD + tr * 8];
            float4 a1 = *(const float4*)&As[kk * AS_LD + tr * 8 + 4];
            float4 b0 = *(const float4*)&Bs[kk * BN + tc * 4];
            float av[8] = {a0.x, a0.y, a0.z, a0.w, a1.x, a1.y, a1.z, a1.w};
            float bv[4] = {b0.x, b0.y, b0.z, b0.w};
#pragma unroll
            for (int i = 0; i < 8; i++)
#pragma unroll
                for (int j = 0; j < 4; j++)
                    acc[i][j] = fmaf(av[i], bv[j], acc[i][j]);
        }
        __syncthreads();
    }

    // Epilogue: add bias, store as float4 (coalesced across tc)
    float4 bias4 = *(const float4*)&brow[block_col + tc * 4];
#pragma unroll
    for (int i = 0; i < 8; i++) {
        int row = block_row + tr * 8 + i;
        int col = block_col + tc * 4;
        float4 o;
        o.x = acc[i][0] + bias4.x;
        o.y = acc[i][1] + bias4.y;
        o.z = acc[i][2] + bias4.z;
        o.w = acc[i][3] + bias4.w;
        float* dst = (z == 0)
            ? &g_mx[(size_t)row * NX + col]
            : &g_inner[(size_t)row * (R_N * NX) + (size_t)(z - 1) * NX + col];
        *(float4*)dst = o;
    }
}

// Fused epilogue: gates, hh, 5-way logits (block reduction), masked softmax,
// weighted sum of the output bank. One block per batch row, one thread per unit.
__global__ void __launch_bounds__(256) fuse_kernel(
    const float* __restrict__ states,
    const int* __restrict__ cell_mask,   // bool transported as int32
    const float* __restrict__ v,
    float* __restrict__ out)
{
    const int b = blockIdx.x;
    const int u = threadIdx.x;

    const size_t mx_base = (size_t)b * NX;
    const float x_z = g_mx[mx_base + u];
    const float x_r = g_mx[mx_base + U_N + u];
    const float x_h = g_mx[mx_base + 2 * U_N + u];

    bool m[R_N];
#pragma unroll
    for (int r = 0; r < R_N; r++) m[r] = cell_mask[b * R_N + r] != 0;

    float rz[R_N];
    float acc = 0.f;
#pragma unroll
    for (int r = 0; r < R_N; r++) {
        const size_t base = (size_t)b * (R_N * NX) + (size_t)r * NX;
        rz[r] = g_inner[base + u];
        const float rr  = g_inner[base + U_N + u];
        const float rhc = g_inner[base + 2 * U_N + u];
        if (m[r]) {
            float rg = 1.0f / (1.0f + expf(-(x_r + rr)));
            acc += rg * rhc;
        }
    }
    const float hh = tanhf(x_h + acc * (1.0f / R_N));

    const float vu = v[u];
    float part[R_N + 1];
#pragma unroll
    for (int r = 0; r < R_N; r++) part[r] = tanhf(x_z + rz[r]) * vu;
    part[R_N] = tanhf(x_z + hh) * vu;

    __shared__ float wsum[R_N + 1][8];
    const int lane = u & 31;
    const int wid = u >> 5;
#pragma unroll
    for (int k = 0; k < R_N + 1; k++) {
        float s = part[k];
#pragma unroll
        for (int off = 16; off > 0; off >>= 1)
            s += __shfl_down_sync(0xffffffffu, s, off);
        if (lane == 0) wsum[k][wid] = s;
    }
    __shared__ float prob_s[R_N + 1];
    __syncthreads();
    if (u == 0) {
        float logit[R_N + 1];
        float mx = -INFINITY;
#pragma unroll
        for (int k = 0; k < R_N + 1; k++) {
            float s = 0.f;
#pragma unroll
            for (int w = 0; w < 8; w++) s += wsum[k][w];
            const bool ok = (k == R_N) ? true : m[k];
            logit[k] = ok ? s : -INFINITY;
            mx = fmaxf(mx, logit[k]);
        }
        float denom = 0.f;
        float e[R_N + 1];
#pragma unroll
        for (int k = 0; k < R_N + 1; k++) {
            e[k] = (logit[k] == -INFINITY) ? 0.f : expf(logit[k] - mx);
            denom += e[k];
        }
#pragma unroll
        for (int k = 0; k < R_N + 1; k++) prob_s[k] = e[k] / denom;
    }
    __syncthreads();

    float h = 0.f;
#pragma unroll
    for (int r = 0; r < R_N; r++)
        h += states[(size_t)b * (R_N * U_N) + r * U_N + u] * prob_s[r];
    h += hh * prob_s[R_N];
    out[(size_t)b * U_N + u] = h;
}

extern "C" void kernel_launch(void* const* d_in, const int* in_sizes, int n_in,
                              void* d_out, int out_size) {
    const float* inputs    = (const float*)d_in[0];
    const float* states    = (const float*)d_in[1];
    /* d_in[2] = edge_types (int32, dead in reference) */
    const int*   cell_mask = (const int*)d_in[3];      // bool -> int32 transport
    const float* kernelW   = (const float*)d_in[4];
    const float* rkernel   = (const float*)d_in[5];
    const float* bias      = (const float*)d_in[6];
    const float* v         = (const float*)d_in[7];
    /* d_in[8] = edge_emb (dead in reference) */
    float* out = (float*)d_out;
    (void)in_sizes; (void)n_in; (void)out_size;

    dim3 ggrid(NX / BN, B_ROWS / BM, 5);   // 12 x 256 x 5
    gemm5_kernel<<<ggrid, 256>>>(inputs, states, kernelW, rkernel, bias);
    fuse_kernel<<<B_ROWS, 256>>>(states, cell_mask, v, out);
}

// round 4
// speedup vs baseline: 3.3103x; 3.3103x over previous
#include <cuda_runtime.h>
#include <cuda_bf16.h>
#include <cstdint>
#include <math.h>

#define B_ROWS 32768
#define R_N 4
#define U_N 256
#define D_N 256
#define NX 768  /* 3*U */
#define NZ 5
#define MT_N 256   /* M tiles: 32768/128 */
#define NT_N 6     /* N tiles: 768/128 */
#define KC_N 4     /* K chunks: 256/64 */

// tcgen05 is an arch-specific feature: only compile it into the sm_103a cubin
// pass. The generic compute_103 PTX pass gets a correct fp32 fallback (never
// executed when the exact-match cubin is present).
#if defined(__CUDA_ARCH__) && (defined(__CUDA_ARCH_FEAT_SM103_ALL) || \
    defined(__CUDA_ARCH_FEAT_SM100_ALL) || defined(__CUDA_ARCH_SPECIFIC__))
#define HAS_TCGEN05 1
#else
#define HAS_TCGEN05 0
#endif

// ---------------- global scratch (allowed: __device__ globals) ----------------
__device__ float g_mx[(size_t)B_ROWS * NX];              // matrix_x  (B, 768)
__device__ float g_inner[(size_t)B_ROWS * R_N * NX];     // matrix_inner (B, 4, 768)

// Pre-swizzled bf16 tiles. Each tile: 128 rows x 128 bytes (64 bf16), SW128,
// stored as 1024 uint4. A tiles: [z][mt][kc]; W tiles: [z][nt][kc].
__device__ uint4 gA_hi[(size_t)NZ * MT_N * KC_N * 1024];   // 80 MB
__device__ uint4 gA_lo[(size_t)NZ * MT_N * KC_N * 1024];   // 80 MB
__device__ uint4 gW_hi[(size_t)NZ * NT_N * KC_N * 1024];   // ~2 MB
__device__ uint4 gW_lo[(size_t)NZ * NT_N * KC_N * 1024];

// ---------------- PTX helpers ----------------
static __device__ __forceinline__ uint32_t smem_u32(const void* p) {
    uint32_t a;
    asm("{ .reg .u64 t; cvta.to.shared.u64 t, %1; cvt.u32.u64 %0, t; }" : "=r"(a) : "l"(p));
    return a;
}
static __device__ __forceinline__ uint32_t elect1() {
    uint32_t p;
    asm volatile("{\n\t.reg .pred p;\n\telect.sync _|p, 0xFFFFFFFF;\n\tselp.b32 %0, 1, 0, p;\n\t}" : "=r"(p));
    return p;
}
// SW128, Blackwell, LBO=1, SBO=64 (K-major, 128-byte rows)
#define SMEM_DESC_BASE ((2ull<<61)|(1ull<<46)|(64ull<<32)|(1ull<<16))
static __device__ __forceinline__ uint64_t make_desc(uint32_t addr) {
    return SMEM_DESC_BASE | ((uint64_t)(addr >> 4) & 0x3FFFull);
}
// idesc: dtype F32, atype/btype BF16, N=128, M=128
#define IDESC_BF16 ((1u<<4)|(1u<<7)|(1u<<10)|((128u/8u)<<17)|((128u/16u)<<24))

#define MBAR_INIT(addr, cnt) \
    asm volatile("mbarrier.init.shared.b64 [%0], %1;" :: "r"(addr), "r"(cnt) : "memory")
#define MBAR_INVAL(addr) \
    asm volatile("mbarrier.inval.shared.b64 [%0];" :: "r"(addr) : "memory")
#define MBAR_WAIT(addr, parity) do {                                              \
    uint32_t _m = (addr), _p = (parity), _d;                                      \
    asm volatile("{\n\t.reg .pred p;\n\t"                                         \
        "mbarrier.try_wait.parity.acquire.cta.shared::cta.b64 p, [%1], %2;\n\t"   \
        "selp.b32 %0, 1, 0, p;\n\t}" : "=r"(_d) : "r"(_m), "r"(_p) : "memory");   \
    if (!_d) {                                                                    \
        asm volatile("{\n\t.reg .pred P1;\n\t"                                    \
            "WL_%=:\n\t"                                                          \
            "mbarrier.try_wait.parity.acquire.cta.shared::cta.b64 P1, [%0], %1, 0x989680;\n\t" \
            "@P1 bra.uni WD_%=;\n\t"                                              \
            "bra.uni WL_%=;\n\t"                                                  \
            "WD_%=:\n\t}" :: "r"(_m), "r"(_p) : "memory");                        \
    } } while (0)

#if HAS_TCGEN05
static __device__ __forceinline__ void mma_f16_ss(uint32_t d_tmem, uint64_t a_desc,
                                                  uint64_t b_desc, uint32_t en) {
    asm volatile(
        "{\n\t"
        ".reg .pred p;\n\t"
        "setp.ne.u32 p, %4, 0;\n\t"
        "tcgen05.mma.cta_group::1.kind::f16 [%0], %1, %2, %3, {%5, %5, %5, %5}, p;\n\t"
        "}"
        :: "r"(d_tmem), "l"(a_desc), "l"(b_desc), "r"(IDESC_BF16), "r"(en), "r"(0u)
        : "memory");
}

#define TC_LD_X32(r, addr)                                                        \
    asm volatile("tcgen05.ld.sync.aligned.32x32b.x32.b32 "                        \
        "{%0, %1, %2, %3, %4, %5, %6, %7, "                                       \
        " %8, %9, %10, %11, %12, %13, %14, %15, "                                 \
        " %16, %17, %18, %19, %20, %21, %22, %23, "                               \
        " %24, %25, %26, %27, %28, %29, %30, %31}, [%32];"                        \
        : "=r"((r)[0]),  "=r"((r)[1]),  "=r"((r)[2]),  "=r"((r)[3]),              \
          "=r"((r)[4]),  "=r"((r)[5]),  "=r"((r)[6]),  "=r"((r)[7]),              \
          "=r"((r)[8]),  "=r"((r)[9]),  "=r"((r)[10]), "=r"((r)[11]),             \
          "=r"((r)[12]), "=r"((r)[13]), "=r"((r)[14]), "=r"((r)[15]),             \
          "=r"((r)[16]), "=r"((r)[17]), "=r"((r)[18]), "=r"((r)[19]),             \
          "=r"((r)[20]), "=r"((r)[21]), "=r"((r)[22]), "=r"((r)[23]),             \
          "=r"((r)[24]), "=r"((r)[25]), "=r"((r)[26]), "=r"((r)[27]),             \
          "=r"((r)[28]), "=r"((r)[29]), "=r"((r)[30]), "=r"((r)[31])              \
        : "r"(addr))
#endif

// ---------------- prep kernels: fp32 -> bf16 hi/lo, pre-swizzled tiles ----------------
__global__ void __launch_bounds__(256) prep_A(const float* __restrict__ inputs,
                                              const float* __restrict__ states) {
    unsigned i = blockIdx.x * 256u + threadIdx.x;     // < 5*256*4*128*8 = 5242880
    unsigned g  = i & 7u;
    unsigned r  = (i >> 3) & 127u;
    unsigned kc = (i >> 10) & 3u;
    unsigned mt = (i >> 12) & 255u;
    unsigned z  = i >> 20;
    unsigned b  = mt * 128u + r;
    unsigned k0 = kc * 64u + g * 8u;
    const float* src = (z == 0) ? inputs + (size_t)b * D_N + k0
                                : states + ((size_t)b * R_N + (z - 1)) * U_N + k0;
    float4 f0 = *(const float4*)src;
    float4 f1 = *(const float4*)(src + 4);
    float x[8] = {f0.x, f0.y, f0.z, f0.w, f1.x, f1.y, f1.z, f1.w};
    unsigned hs[8], ls[8];
#pragma unroll
    for (int j = 0; j < 8; j++) {
        __nv_bfloat16 h = __float2bfloat16_rn(x[j]);
        hs[j] = (unsigned)__bfloat16_as_ushort(h);
        float hf = __bfloat162float(h);
        ls[j] = (unsigned)__bfloat16_as_ushort(__float2bfloat16_rn(x[j] - hf));
    }
    uint4 uh, ul;
    uh.x = hs[0] | (hs[1] << 16); uh.y = hs[2] | (hs[3] << 16);
    uh.z = hs[4] | (hs[5] << 16); uh.w = hs[6] | (hs[7] << 16);
    ul.x = ls[0] | (ls[1] << 16); ul.y = ls[2] | (ls[3] << 16);
    ul.z = ls[4] | (ls[5] << 16); ul.w = ls[6] | (ls[7] << 16);
    unsigned byte = (i & 1023u) * 16u;                 // r*128 + g*16
    unsigned sw = byte ^ ((byte >> 3) & 0x70u);        // SW128
    size_t t = (size_t)(i >> 10);
    gA_hi[t * 1024 + (sw >> 4)] = uh;
    gA_lo[t * 1024 + (sw >> 4)] = ul;
}

__global__ void __launch_bounds__(256) prep_W(const float* __restrict__ kernelW,
                                              const float* __restrict__ rkernel) {
    unsigned i = blockIdx.x * 256u + threadIdx.x;      // < 5*6*4*128*8 = 122880
    unsigned g   = i & 7u;
    unsigned nr  = (i >> 3) & 127u;
    unsigned top = i >> 10;           // (z*6+nt)*4+kc
    unsigned kc  = top & 3u;
    unsigned tz  = top >> 2;
    unsigned z   = tz / 6u;
    unsigned nt  = tz % 6u;
    unsigned ncol = nt * 128u + nr;
    unsigned hs[8], ls[8];
#pragma unroll
    for (int j = 0; j < 8; j++) {
        unsigned k = kc * 64u + g * 8u + j;
        float x = (z == 0) ? kernelW[(size_t)k * NX + ncol]
                           : rkernel[((size_t)(z - 1) * U_N + k) * NX + ncol];
        __nv_bfloat16 h = __float2bfloat16_rn(x);
        hs[j] = (unsigned)__bfloat16_as_ushort(h);
        float hf = __bfloat162float(h);
        ls[j] = (unsigned)__bfloat16_as_ushort(__float2bfloat16_rn(x - hf));
    }
    uint4 uh, ul;
    uh.x = hs[0] | (hs[1] << 16); uh.y = hs[2] | (hs[3] << 16);
    uh.z = hs[4] | (hs[5] << 16); uh.w = hs[6] | (hs[7] << 16);
    ul.x = ls[0] | (ls[1] << 16); ul.y = ls[2] | (ls[3] << 16);
    ul.z = ls[4] | (ls[5] << 16); ul.w = ls[6] | (ls[7] << 16);
    unsigned byte = (i & 1023u) * 16u;
    unsigned sw = byte ^ ((byte >> 3) & 0x70u);
    gW_hi[(size_t)top * 1024 + (sw >> 4)] = uh;
    gW_lo[(size_t)top * 1024 + (sw >> 4)] = ul;
}

// Read bf16 element (row, k-col) out of a SW128-swizzled tile in smem (fallback path).
static __device__ __forceinline__ float rd_bf16_sw(const char* base, int row, int col) {
    unsigned byte = (unsigned)row * 128u + (unsigned)col * 2u;
    unsigned sw = byte ^ ((byte >> 3) & 0x70u);
    unsigned short u = *(const unsigned short*)(base + sw);
    return __bfloat162float(__ushort_as_bfloat16(u));
}

// ---------------- tcgen05 GEMM: D(128x128 fp32 in TMEM) = A(128x256) * W(256x128) ----------------
// 3 bf16 passes per K16-step: Ah*Wh + Ah*Wl + Al*Wh  (split-precision, ~1e-5 rel err)
#define DSMEM_BYTES 67584

__global__ void __launch_bounds__(256) gemm_tc(const float* __restrict__ bias) {
    extern __shared__ __align__(16) char smem[];
    const uint32_t sb = smem_u32(smem);
    const int tid = threadIdx.x, wid = tid >> 5, lane = tid & 31;
    const int nt = blockIdx.x, mt = blockIdx.y, z = blockIdx.z;

    // tiles base: 1024-aligned shared address
    const uint32_t tb = (sb + 1024u + 1023u) & ~1023u;
    char* tbp = smem + (tb - sb);

#if HAS_TCGEN05
    if (wid == 0) {
        asm volatile("tcgen05.alloc.cta_group::1.sync.aligned.shared::cta.b32 [%0], %1;"
                     :: "r"(sb), "r"(128u) : "memory");
        asm volatile("tcgen05.relinquish_alloc_permit.cta_group::1.sync.aligned;");
    }
    if (tid == 0) MBAR_INIT(sb + 8, 1u);
    __syncthreads();
    uint32_t tmem;
    asm volatile("ld.shared.b32 %0, [%1];" : "=r"(tmem) : "r"(sb));
#else
    float facc[64];
#pragma unroll
    for (int j = 0; j < 64; j++) facc[j] = 0.f;
#endif

    uint4* sAh = (uint4*)(tbp);
    uint4* sAl = (uint4*)(tbp + 16384);
    uint4* sBh = (uint4*)(tbp + 32768);
    uint4* sBl = (uint4*)(tbp + 49152);
#if HAS_TCGEN05
    const uint64_t dAh = make_desc(tb);
    const uint64_t dAl = make_desc(tb + 16384);
    const uint64_t dBh = make_desc(tb + 32768);
    const uint64_t dBl = make_desc(tb + 49152);
#endif

    for (int kc = 0; kc < KC_N; kc++) {
#if HAS_TCGEN05
        if (kc > 0) MBAR_WAIT(sb + 8, (unsigned)((kc - 1) & 1));
#endif
        const size_t tA = ((size_t)((z * MT_N + mt) * KC_N + kc)) * 1024;
        const size_t tB = ((size_t)((z * NT_N + nt) * KC_N + kc)) * 1024;
#pragma unroll
        for (int j = 0; j < 4; j++) {
            int idx = tid + j * 256;
            sAh[idx] = gA_hi[tA + idx];
            sAl[idx] = gA_lo[tA + idx];
            sBh[idx] = gW_hi[tB + idx];
            sBl[idx] = gW_lo[tB + idx];
        }
        asm volatile("fence.proxy.async.shared::cta;" ::: "memory");
        __syncthreads();
#if HAS_TCGEN05
        if (wid == 0 && elect1()) {
#pragma unroll
            for (int ks = 0; ks < 4; ks++) {
                uint64_t off = (uint64_t)(ks * 2);
                mma_f16_ss(tmem, dAh + off, dBh + off, (kc == 0 && ks == 0) ? 0u : 1u);
                mma_f16_ss(tmem, dAh + off, dBl + off, 1u);
                mma_f16_ss(tmem, dAl + off, dBh + off, 1u);
            }
            asm volatile(
                "tcgen05.commit.cta_group::1.mbarrier::arrive::one.shared::cluster.b64 [%0];"
                :: "r"(sb + 8) : "memory");
        }
#else
        // fp32 fallback: thread handles row=tid>>1, cols (tid&1)*64..+63
        {
            const int frow = tid >> 1;
            const int fc0 = (tid & 1) * 64;
            for (int kk = 0; kk < 64; kk++) {
                float a = rd_bf16_sw((const char*)sAh, frow, kk)
                        + rd_bf16_sw((const char*)sAl, frow, kk);
#pragma unroll 8
                for (int j = 0; j < 64; j++) {
                    float bb = rd_bf16_sw((const char*)sBh, fc0 + j, kk)
                             + rd_bf16_sw((const char*)sBl, fc0 + j, kk);
                    facc[j] = fmaf(a, bb, facc[j]);
                }
            }
            __syncthreads();
        }
#endif
    }

#if HAS_TCGEN05
    MBAR_WAIT(sb + 8, 1u);   // 4th commit -> phase 3 (parity 1)
    asm volatile("tcgen05.fence::after_thread_sync;" ::: "memory");

    // Epilogue: TMEM -> swizzled SMEM staging -> coalesced global with bias.
    // warp w: rows (w&3)*32+lane, cols (w>>2)*64 .. +63
    const int cb = (wid >> 2) * 64;
    const int row = (wid & 3) * 32 + lane;
#pragma unroll
    for (int half = 0; half < 2; half++) {
        uint32_t r[32];
        TC_LD_X32(r, tmem + (uint32_t)(cb + half * 32));
        asm volatile("tcgen05.wait::ld.sync.aligned;" ::: "memory");
#pragma unroll
        for (int q = 0; q < 8; q++) {
            int col = cb + half * 32 + q * 4;
            unsigned byte = (unsigned)row * 512u + (unsigned)col * 4u;
            unsigned phys = byte ^ (((unsigned)row & 7u) << 4);
            *(uint4*)(tbp + phys) = make_uint4(r[q*4+0], r[q*4+1], r[q*4+2], r[q*4+3]);
        }
    }
    __syncthreads();
    const int n0 = nt * 128;
#pragma unroll
    for (int it = 0; it < 16; it++) {
        int i2 = tid + it * 256;
        int rw = i2 >> 5, c4 = i2 & 31;
        unsigned byte = (unsigned)rw * 512u + (unsigned)c4 * 16u;
        unsigned phys = byte ^ (((unsigned)rw & 7u) << 4);
        uint4 v = *(const uint4*)(tbp + phys);
        float4 f;
        f.x = __uint_as_float(v.x); f.y = __uint_as_float(v.y);
        f.z = __uint_as_float(v.z); f.w = __uint_as_float(v.w);
        const float4 b4 = *(const float4*)(bias + (size_t)z * NX + n0 + c4 * 4);
        f.x += b4.x; f.y += b4.y; f.z += b4.z; f.w += b4.w;
        size_t rg = (size_t)mt * 128 + rw;
        float* dst = (z == 0)
            ? (g_mx + rg * NX + n0 + c4 * 4)
            : (g_inner + rg * (R_N * NX) + (size_t)(z - 1) * NX + n0 + c4 * 4);
        *(float4*)dst = f;
    }
    __syncthreads();
    if (tid == 0) MBAR_INVAL(sb + 8);
    __syncthreads();
    if (wid == 0) {
        asm volatile("tcgen05.dealloc.cta_group::1.sync.aligned.b32 %0, %1;"
                     :: "r"(tmem), "r"(128u));
    }
#else
    // fallback epilogue: direct store with bias
    {
        const int frow = tid >> 1;
        const int fc0 = (tid & 1) * 64;
        const int n0 = nt * 128;
        size_t rg = (size_t)mt * 128 + frow;
#pragma unroll 8
        for (int j = 0; j < 64; j++) {
            float f = facc[j] + bias[(size_t)z * NX + n0 + fc0 + j];
            float* dst = (z == 0)
                ? (g_mx + rg * NX + n0 + fc0 + j)
                : (g_inner + rg * (R_N * NX) + (size_t)(z - 1) * NX + n0 + fc0 + j);
            *dst = f;
        }
    }
#endif
}

// ---------------- fused epilogue (unchanged from passing round) ----------------
__global__ void __launch_bounds__(256) fuse_kernel(
    const float* __restrict__ states,
    const int* __restrict__ cell_mask,
    const float* __restrict__ v,
    float* __restrict__ out)
{
    const int b = blockIdx.x;
    const int u = threadIdx.x;

    const size_t mx_base = (size_t)b * NX;
    const float x_z = g_mx[mx_base + u];
    const float x_r = g_mx[mx_base + U_N + u];
    const float x_h = g_mx[mx_base + 2 * U_N + u];

    bool m[R_N];
#pragma unroll
    for (int r = 0; r < R_N; r++) m[r] = cell_mask[b * R_N + r] != 0;

    float rz[R_N];
    float acc = 0.f;
#pragma unroll
    for (int r = 0; r < R_N; r++) {
        const size_t base = (size_t)b * (R_N * NX) + (size_t)r * NX;
        rz[r] = g_inner[base + u];
        const float rr  = g_inner[base + U_N + u];
        const float rhc = g_inner[base + 2 * U_N + u];
        if (m[r]) {
            float rg = 1.0f / (1.0f + expf(-(x_r + rr)));
            acc += rg * rhc;
        }
    }
    const float hh = tanhf(x_h + acc * (1.0f / R_N));

    const float vu = v[u];
    float part[R_N + 1];
#pragma unroll
    for (int r = 0; r < R_N; r++) part[r] = tanhf(x_z + rz[r]) * vu;
    part[R_N] = tanhf(x_z + hh) * vu;

    __shared__ float wsum[R_N + 1][8];
    const int lane = u & 31;
    const int wid = u >> 5;
#pragma unroll
    for (int k = 0; k < R_N + 1; k++) {
        float s = part[k];
#pragma unroll
        for (int off = 16; off > 0; off >>= 1)
            s += __shfl_down_sync(0xffffffffu, s, off);
        if (lane == 0) wsum[k][wid] = s;
    }
    __shared__ float prob_s[R_N + 1];
    __syncthreads();
    if (u == 0) {
        float logit[R_N + 1];
        float mx = -INFINITY;
#pragma unroll
        for (int k = 0; k < R_N + 1; k++) {
            float s = 0.f;
#pragma unroll
            for (int w = 0; w < 8; w++) s += wsum[k][w];
            const bool ok = (k == R_N) ? true : m[k];
            logit[k] = ok ? s : -INFINITY;
            mx = fmaxf(mx, logit[k]);
        }
        float denom = 0.f;
        float e[R_N + 1];
#pragma unroll
        for (int k = 0; k < R_N + 1; k++) {
            e[k] = (logit[k] == -INFINITY) ? 0.f : expf(logit[k] - mx);
            denom += e[k];
        }
#pragma unroll
        for (int k = 0; k < R_N + 1; k++) prob_s[k] = e[k] / denom;
    }
    __syncthreads();

    float h = 0.f;
#pragma unroll
    for (int r = 0; r < R_N; r++)
        h += states[(size_t)b * (R_N * U_N) + r * U_N + u] * prob_s[r];
    h += hh * prob_s[R_N];
    out[(size_t)b * U_N + u] = h;
}

extern "C" void kernel_launch(void* const* d_in, const int* in_sizes, int n_in,
                              void* d_out, int out_size) {
    const float* inputs    = (const float*)d_in[0];
    const float* states    = (const float*)d_in[1];
    /* d_in[2] = edge_types (dead in reference) */
    const int*   cell_mask = (const int*)d_in[3];
    const float* kernelW   = (const float*)d_in[4];
    const float* rkernel   = (const float*)d_in[5];
    const float* bias      = (const float*)d_in[6];
    const float* v         = (const float*)d_in[7];
    /* d_in[8] = edge_emb (dead in reference) */
    float* out = (float*)d_out;
    (void)in_sizes; (void)n_in; (void)out_size;

    cudaFuncSetAttribute(gemm_tc, cudaFuncAttributeMaxDynamicSharedMemorySize, DSMEM_BYTES);

    prep_W<<<480, 256>>>(kernelW, rkernel);
    prep_A<<<20480, 256>>>(inputs, states);
    gemm_tc<<<dim3(NT_N, MT_N, NZ), 256, DSMEM_BYTES>>>(bias);
    fuse_kernel<<<B_ROWS, 256>>>(states, cell_mask, v, out);
}